// round 14
// baseline (speedup 1.0000x reference)
#include <cuda_runtime.h>
#include <cuda_bf16.h>
#include <cstdint>

// QuantizedEmbedding: out[i, d] = code[quant_weight[x[i], d]] * absmax[x[i] >> 2]
//   x: int32[16384]  qw: int32[50304,1024]  absmax: f32[12576]  code: f32[256]
//   out: f32[16384,1024]   (block index == v>>2 since (v%4)*1024 + d < 4096)
//
// R14: 256-bit memory ops (sm_100+ LDG.256/STG.256 via PTX v8 vectors).
// Each thread owns a 32B chunk (8 codes -> 8 floats): LDG and STG instruction
// counts per token halve (8->4), attacking the measured LSU-issue equilibrium
// (STG.128 issue = 12cyc was the largest per-token MIO term).
// Structure = R5/R11: persistent CTAs, double-buffered group prefetch,
// 8-way interleaved codebook, .cs streaming stores (proven load-bearing).
// 128 threads per token row; 2 tokens per group.

#define TOKG 2   // tokens per group (one per thread-half)

__global__ void __launch_bounds__(256, 4)
qembed_kernel(const int* __restrict__ x,
              const unsigned* __restrict__ qw,   // int32 codes, 1024 per row
              const float* __restrict__ absmax,
              const float* __restrict__ code,
              float* __restrict__ out,
              int n_groups)
{
    __shared__ float s_code[256 * 8];
    const int t    = threadIdx.x;
    const int c    = t & 7;          // lane class -> private 4-bank set
    const int half = t >> 7;         // which of the 2 tokens in the group
    const int s    = t & 127;        // 32B-chunk index within the row

    {
        const float cv = code[t];
        #pragma unroll
        for (int r = 0; r < 8; r++)
            s_code[t * 8 + r] = cv;
    }
    __syncthreads();

    const int G = gridDim.x;
    int g = blockIdx.x;

    unsigned q[8];
    float    sc;

    // Prefetch first group: one 256-bit load of 8 codes.
    {
        const int v = x[g * TOKG + half];
        const unsigned* p = qw + (size_t)v * 1024 + s * 8;
        asm volatile("ld.global.nc.v8.u32 {%0,%1,%2,%3,%4,%5,%6,%7}, [%8];"
                     : "=r"(q[0]), "=r"(q[1]), "=r"(q[2]), "=r"(q[3]),
                       "=r"(q[4]), "=r"(q[5]), "=r"(q[6]), "=r"(q[7])
                     : "l"(p));
        sc = __ldg(&absmax[v >> 2]);
    }

    while (true) {
        const int gn = g + G;

        unsigned qn[8];
        float    scn;
        if (gn < n_groups) {
            const int v = x[gn * TOKG + half];
            const unsigned* p = qw + (size_t)v * 1024 + s * 8;
            asm volatile("ld.global.nc.v8.u32 {%0,%1,%2,%3,%4,%5,%6,%7}, [%8];"
                         : "=r"(qn[0]), "=r"(qn[1]), "=r"(qn[2]), "=r"(qn[3]),
                           "=r"(qn[4]), "=r"(qn[5]), "=r"(qn[6]), "=r"(qn[7])
                         : "l"(p));
            scn = __ldg(&absmax[v >> 2]);
        }

        // Dequant 8 values, one 256-bit streaming store.
        {
            float o[8];
            #pragma unroll
            for (int i = 0; i < 8; i++)
                o[i] = s_code[q[i] * 8 + c] * sc;

            float* gp = out + (size_t)(g * TOKG + half) * 1024 + s * 8;
            asm volatile("st.global.cs.v8.f32 [%0], {%1,%2,%3,%4,%5,%6,%7,%8};"
                         :: "l"(gp),
                            "f"(o[0]), "f"(o[1]), "f"(o[2]), "f"(o[3]),
                            "f"(o[4]), "f"(o[5]), "f"(o[6]), "f"(o[7])
                         : "memory");
        }

        if (gn >= n_groups) break;
        g = gn;
        #pragma unroll
        for (int i = 0; i < 8; i++) q[i] = qn[i];
        sc = scn;
    }
}

extern "C" void kernel_launch(void* const* d_in, const int* in_sizes, int n_in,
                              void* d_out, int out_size)
{
    // Bind inputs by element count (all four distinct) — robust to ordering.
    const int*      x      = nullptr;  int n_tokens = 0;
    const unsigned* qw     = nullptr;
    const float*    absmax = nullptr;
    const float*    code   = nullptr;

    for (int i = 0; i < n_in; i++) {
        const int sz = in_sizes[i];
        if (sz == 256)            code   = (const float*)d_in[i];
        else if (sz == 12576)     absmax = (const float*)d_in[i];
        else if (sz > 1000000)    qw     = (const unsigned*)d_in[i];
        else                      { x = (const int*)d_in[i]; n_tokens = sz; }
    }

    float* out = (float*)d_out;
    const int n_groups = n_tokens / TOKG;        // 8192
    const int grid = 148 * 4;                    // persistent: one wave at occ 4
    qembed_kernel<<<grid, 256>>>(x, qw, absmax, code, out, n_groups);
}

// round 15
// speedup vs baseline: 1.5389x; 1.5389x over previous
#include <cuda_runtime.h>
#include <cuda_bf16.h>
#include <cstdint>

// QuantizedEmbedding: out[i, d] = code[quant_weight[x[i], d]] * absmax[x[i] >> 2]
//   x: int32[16384]  qw: int32[50304,1024]  absmax: f32[12576]  code: f32[256]
//   out: f32[16384,1024]   (block index == v>>2 since (v%4)*1024 + d < 4096)
//
// R15: the untested matrix cell — persistent + double-buffered + HIGH OCC.
// TOK=2 per group shrinks the prefetch buffer to 16 regs, so the kernel fits
// launch_bounds(256,6): 48 warps/SM (occ ~65%) with the R5 pipeline intact.
// 8-way interleaved codebook, __ldcg reads, __stcs streaming stores (proven).

#define TOK 2

__global__ void __launch_bounds__(256, 6)
qembed_kernel(const int* __restrict__ x,
              const int4* __restrict__ qw,
              const float* __restrict__ absmax,
              const float* __restrict__ code,
              float4* __restrict__ out,
              int n_groups)
{
    __shared__ float s_code[256 * 8];
    const int t = threadIdx.x;
    const int c = t & 7;               // lane class -> private 4-bank set

    {
        const float cv = code[t];
        #pragma unroll
        for (int r = 0; r < 8; r++)
            s_code[t * 8 + r] = cv;
    }
    __syncthreads();

    const int G = gridDim.x;
    int g = blockIdx.x;

    // Prefetch first group.
    int4  q[TOK];
    float sc[TOK];
    #pragma unroll
    for (int k = 0; k < TOK; k++) {
        const int v = x[g * TOK + k];
        q[k]  = __ldcg(&qw[(size_t)v * 256 + t]);
        sc[k] = __ldg(&absmax[v >> 2]);
    }

    while (true) {
        const int gn = g + G;

        int4  qn[TOK];
        float scn[TOK];
        if (gn < n_groups) {
            // Issue next group's independent loads before processing current.
            #pragma unroll
            for (int k = 0; k < TOK; k++) {
                const int v = x[gn * TOK + k];
                qn[k]  = __ldcg(&qw[(size_t)v * 256 + t]);
                scn[k] = __ldg(&absmax[v >> 2]);
            }
        }

        // Process current group (LDS lookups + streaming stores).
        #pragma unroll
        for (int k = 0; k < TOK; k++) {
            float4 o;
            o.x = s_code[q[k].x * 8 + c] * sc[k];
            o.y = s_code[q[k].y * 8 + c] * sc[k];
            o.z = s_code[q[k].z * 8 + c] * sc[k];
            o.w = s_code[q[k].w * 8 + c] * sc[k];
            __stcs(&out[(size_t)(g * TOK + k) * 256 + t], o);
        }

        if (gn >= n_groups) break;
        g = gn;
        #pragma unroll
        for (int k = 0; k < TOK; k++) { q[k] = qn[k]; sc[k] = scn[k]; }
    }
}

extern "C" void kernel_launch(void* const* d_in, const int* in_sizes, int n_in,
                              void* d_out, int out_size)
{
    // Bind inputs by element count (all four distinct) — robust to ordering.
    const int*   x      = nullptr;  int n_tokens = 0;
    const int4*  qw     = nullptr;
    const float* absmax = nullptr;
    const float* code   = nullptr;

    for (int i = 0; i < n_in; i++) {
        const int sz = in_sizes[i];
        if (sz == 256)            code   = (const float*)d_in[i];
        else if (sz == 12576)     absmax = (const float*)d_in[i];
        else if (sz > 1000000)    qw     = (const int4*)d_in[i];
        else                      { x = (const int*)d_in[i]; n_tokens = sz; }
    }

    float4* out = (float4*)d_out;
    const int n_groups = n_tokens / TOK;         // 8192
    const int grid = 148 * 6;                    // persistent: one wave at occ 6
    qembed_kernel<<<grid, 256>>>(x, qw, absmax, code, out, n_groups);
}